// round 15
// baseline (speedup 1.0000x reference)
#include <cuda_runtime.h>
#include <cuda_fp16.h>
#include <cstdint>

#define IN_CH   512
#define HID     16
#define OUT_CH  2
#define MAX_NODES 100000

// Scratch (device globals; no allocation allowed)
__device__ __align__(16) float    g_s[MAX_NODES * 2]; // y = x@W12 (fp32)
__device__ __align__(16) unsigned g_sh[MAX_NODES];    // half2(y*dinv) gather table
__device__ __align__(16) int      g_deg[MAX_NODES];   // zero-init; re-zeroed in finalize
__device__ __align__(16) float    g_dinv[MAX_NODES];  // 1/sqrt(deg+1)
__device__ __align__(16) float    g_w0[IN_CH];        // col 0 of W12 = W1@W2
__device__ __align__(16) float    g_w1[IN_CH];        // col 1 of W12
__device__ float g_c[2];                              // b1@W2 + b2

// ---------------------------------------------------------------------------
// zero the output accumulator (runs first on side stream, concurrent w/ prep)
__global__ void zero_kernel(float4* __restrict__ out4, int n4) {
    int i = blockIdx.x * blockDim.x + threadIdx.x;
    if (i < n4) out4[i] = make_float4(0.f, 0.f, 0.f, 0.f);
}

// ---------------------------------------------------------------------------
// degree atomics (side stream)
__global__ void deg_kernel(const int* __restrict__ col, int n_edges) {
    int t = blockIdx.x * blockDim.x + threadIdx.x;
    int n4 = n_edges >> 2;
    if (t < n4) {
        int4 c = __ldcs(reinterpret_cast<const int4*>(col) + t);
        atomicAdd(&g_deg[c.x], 1);
        atomicAdd(&g_deg[c.y], 1);
        atomicAdd(&g_deg[c.z], 1);
        atomicAdd(&g_deg[c.w], 1);
    }
    if (t < (n_edges & 3))
        atomicAdd(&g_deg[col[(n4 << 2) + t]], 1);
}

// dinv = rsqrt(deg+1)  (side stream, right after deg)
__global__ void dinv_kernel(int n_nodes) {
    int i = blockIdx.x * blockDim.x + threadIdx.x;
    if (i < n_nodes) g_dinv[i] = rsqrtf((float)(g_deg[i] + 1));
}

// ---------------------------------------------------------------------------
// fold weights/bias (single block, 512 threads)
__global__ void prep_kernel(const float* __restrict__ W1,
                            const float* __restrict__ b1,
                            const float* __restrict__ W2,
                            const float* __restrict__ b2) {
    int t = threadIdx.x;                 // 512 threads == IN_CH
    float s0 = 0.0f, s1 = 0.0f;
#pragma unroll
    for (int h = 0; h < HID; h++) {
        float w = W1[t * HID + h];
        s0 += w * W2[h * OUT_CH + 0];
        s1 += w * W2[h * OUT_CH + 1];
    }
    g_w0[t] = s0;
    g_w1[t] = s1;
    if (t < OUT_CH) {
        float c = b2[t];
#pragma unroll
        for (int h = 0; h < HID; h++) c += b1[h] * W2[h * OUT_CH + t];
        g_c[t] = c;
    }
}

// ---------------------------------------------------------------------------
// GEMM over rows [row_lo, row_lo + n_rows): warp computes 4 rows, evict-first
__global__ void __launch_bounds__(256, 2)
gemm_kernel(const float* __restrict__ x, int row_lo, int n_rows) {
    const int lane  = threadIdx.x & 31;
    const int gwarp = (blockIdx.x * blockDim.x + threadIdx.x) >> 5;
    const int rbase = row_lo + gwarp * 4;
    const int row_hi = row_lo + n_rows;
    if (rbase >= row_hi) return;

    float4 wa[4], wb[4];
#pragma unroll
    for (int j = 0; j < 4; j++) {
        int idx = lane + 32 * j;
        wa[j] = reinterpret_cast<const float4*>(g_w0)[idx];
        wb[j] = reinterpret_cast<const float4*>(g_w1)[idx];
    }

    const float4* x4 = reinterpret_cast<const float4*>(x);

    if (rbase + 4 <= row_hi) {
        float4 v[4][4];
#pragma unroll
        for (int r = 0; r < 4; r++) {
            const float4* xr = x4 + (size_t)(rbase + r) * (IN_CH / 4);
#pragma unroll
            for (int j = 0; j < 4; j++) v[r][j] = __ldcs(xr + lane + 32 * j);
        }
        float s00 = 0.f, s01 = 0.f, s10 = 0.f, s11 = 0.f;
        float s20 = 0.f, s21 = 0.f, s30 = 0.f, s31 = 0.f;
#pragma unroll
        for (int j = 0; j < 4; j++) {
            s00 += v[0][j].x * wa[j].x + v[0][j].y * wa[j].y + v[0][j].z * wa[j].z + v[0][j].w * wa[j].w;
            s01 += v[0][j].x * wb[j].x + v[0][j].y * wb[j].y + v[0][j].z * wb[j].z + v[0][j].w * wb[j].w;
            s10 += v[1][j].x * wa[j].x + v[1][j].y * wa[j].y + v[1][j].z * wa[j].z + v[1][j].w * wa[j].w;
            s11 += v[1][j].x * wb[j].x + v[1][j].y * wb[j].y + v[1][j].z * wb[j].z + v[1][j].w * wb[j].w;
            s20 += v[2][j].x * wa[j].x + v[2][j].y * wa[j].y + v[2][j].z * wa[j].z + v[2][j].w * wa[j].w;
            s21 += v[2][j].x * wb[j].x + v[2][j].y * wb[j].y + v[2][j].z * wb[j].z + v[2][j].w * wb[j].w;
            s30 += v[3][j].x * wa[j].x + v[3][j].y * wa[j].y + v[3][j].z * wa[j].z + v[3][j].w * wa[j].w;
            s31 += v[3][j].x * wb[j].x + v[3][j].y * wb[j].y + v[3][j].z * wb[j].z + v[3][j].w * wb[j].w;
        }
#pragma unroll
        for (int off = 16; off > 0; off >>= 1) {
            s00 += __shfl_xor_sync(0xFFFFFFFFu, s00, off);
            s01 += __shfl_xor_sync(0xFFFFFFFFu, s01, off);
            s10 += __shfl_xor_sync(0xFFFFFFFFu, s10, off);
            s11 += __shfl_xor_sync(0xFFFFFFFFu, s11, off);
            s20 += __shfl_xor_sync(0xFFFFFFFFu, s20, off);
            s21 += __shfl_xor_sync(0xFFFFFFFFu, s21, off);
            s30 += __shfl_xor_sync(0xFFFFFFFFu, s30, off);
            s31 += __shfl_xor_sync(0xFFFFFFFFu, s31, off);
        }
        if (lane < 4) {
            float o0, o1;
            if      (lane == 0) { o0 = s00; o1 = s01; }
            else if (lane == 1) { o0 = s10; o1 = s11; }
            else if (lane == 2) { o0 = s20; o1 = s21; }
            else                { o0 = s30; o1 = s31; }
            reinterpret_cast<float2*>(g_s)[rbase + lane] = make_float2(o0, o1);
        }
    } else {
        for (int row = rbase; row < row_hi; row++) {
            const float4* xr = x4 + (size_t)row * (IN_CH / 4);
            float s0 = 0.f, s1 = 0.f;
#pragma unroll
            for (int j = 0; j < 4; j++) {
                float4 v0 = __ldcs(xr + lane + 32 * j);
                s0 += v0.x * wa[j].x + v0.y * wa[j].y + v0.z * wa[j].z + v0.w * wa[j].w;
                s1 += v0.x * wb[j].x + v0.y * wb[j].y + v0.z * wb[j].z + v0.w * wb[j].w;
            }
#pragma unroll
            for (int off = 16; off > 0; off >>= 1) {
                s0 += __shfl_xor_sync(0xFFFFFFFFu, s0, off);
                s1 += __shfl_xor_sync(0xFFFFFFFFu, s1, off);
            }
            if (lane == 0)
                reinterpret_cast<float2*>(g_s)[row] = make_float2(s0, s1);
        }
    }
}

// ---------------------------------------------------------------------------
// pack g_sh[i] = half2(y[i] * dinv[i]) over [lo, lo+n)
__global__ void pack_kernel(int lo, int n) {
    int i = lo + blockIdx.x * blockDim.x + threadIdx.x;
    if (i >= lo + n) return;
    float di = g_dinv[i];
    float2 y = reinterpret_cast<const float2*>(g_s)[i];
    __half2 h = __floats2half2_rn(y.x * di, y.y * di);
    g_sh[i] = *reinterpret_cast<unsigned*>(&h);
}

// ---------------------------------------------------------------------------
// edge scatter  out[c] += s[r]  for edges with r in [rlo, rhi)
__global__ void scatter_kernel(const int* __restrict__ row,
                               const int* __restrict__ col,
                               float* __restrict__ out,
                               int n_edges, int rlo, int rhi) {
    int t = blockIdx.x * blockDim.x + threadIdx.x;
    int e = t * 4;
    if (e + 3 < n_edges) {
        int4 r = __ldg(reinterpret_cast<const int4*>(row + e));
        int4 c = __ldg(reinterpret_cast<const int4*>(col + e));

        if (r.x >= rlo && r.x < rhi) {
            unsigned p = __ldg(g_sh + r.x);
            float2 s = __half22float2(*reinterpret_cast<__half2*>(&p));
            asm volatile("red.global.add.v2.f32 [%0], {%1, %2};"
                         :: "l"(out + (size_t)c.x * 2), "f"(s.x), "f"(s.y) : "memory");
        }
        if (r.y >= rlo && r.y < rhi) {
            unsigned p = __ldg(g_sh + r.y);
            float2 s = __half22float2(*reinterpret_cast<__half2*>(&p));
            asm volatile("red.global.add.v2.f32 [%0], {%1, %2};"
                         :: "l"(out + (size_t)c.y * 2), "f"(s.x), "f"(s.y) : "memory");
        }
        if (r.z >= rlo && r.z < rhi) {
            unsigned p = __ldg(g_sh + r.z);
            float2 s = __half22float2(*reinterpret_cast<__half2*>(&p));
            asm volatile("red.global.add.v2.f32 [%0], {%1, %2};"
                         :: "l"(out + (size_t)c.z * 2), "f"(s.x), "f"(s.y) : "memory");
        }
        if (r.w >= rlo && r.w < rhi) {
            unsigned p = __ldg(g_sh + r.w);
            float2 s = __half22float2(*reinterpret_cast<__half2*>(&p));
            asm volatile("red.global.add.v2.f32 [%0], {%1, %2};"
                         :: "l"(out + (size_t)c.w * 2), "f"(s.x), "f"(s.y) : "memory");
        }
    } else {
        for (; e < n_edges; e++) {
            int r1 = row[e], c1 = col[e];
            if (r1 >= rlo && r1 < rhi) {
                unsigned p = __ldg(g_sh + r1);
                float2 sv = __half22float2(*reinterpret_cast<__half2*>(&p));
                asm volatile("red.global.add.v2.f32 [%0], {%1, %2};"
                             :: "l"(out + (size_t)c1 * 2), "f"(sv.x), "f"(sv.y) : "memory");
            }
        }
    }
}

// ---------------------------------------------------------------------------
// finalize (2 nodes/thread): out = (out + y*dinv)*dinv + c; re-zero g_deg
__global__ void finalize_kernel(float* __restrict__ out, int n_nodes) {
    int i = (blockIdx.x * blockDim.x + threadIdx.x) * 2;
    float c0 = g_c[0], c1 = g_c[1];
    if (i + 1 < n_nodes) {
        float4 a = *reinterpret_cast<float4*>(out + i * 2);
        float4 y = *reinterpret_cast<float4*>(g_s + i * 2);
        float2 d = *reinterpret_cast<float2*>(g_dinv + i);
        a.x = (a.x + y.x * d.x) * d.x + c0;
        a.y = (a.y + y.y * d.x) * d.x + c1;
        a.z = (a.z + y.z * d.y) * d.y + c0;
        a.w = (a.w + y.w * d.y) * d.y + c1;
        *reinterpret_cast<float4*>(out + i * 2) = a;
        *reinterpret_cast<int2*>(g_deg + i) = make_int2(0, 0);  // ready for replay
    } else if (i < n_nodes) {
        float di = g_dinv[i];
        float2 a = reinterpret_cast<float2*>(out)[i];
        float2 y = reinterpret_cast<const float2*>(g_s)[i];
        a.x = (a.x + y.x * di) * di + c0;
        a.y = (a.y + y.y * di) * di + c1;
        reinterpret_cast<float2*>(out)[i] = a;
        g_deg[i] = 0;
    }
}

// ---------------------------------------------------------------------------
extern "C" void kernel_launch(void* const* d_in, const int* in_sizes, int n_in,
                              void* d_out, int out_size) {
    const float* x  = (const float*)d_in[0];
    const int*   ei = (const int*)d_in[1];   // [2, E]
    const float* W1 = (const float*)d_in[2];
    const float* b1 = (const float*)d_in[3];
    const float* W2 = (const float*)d_in[4];
    const float* b2 = (const float*)d_in[5];
    float* out = (float*)d_out;

    const int n_edges = in_sizes[1] / 2;
    const int n_nodes = out_size / OUT_CH;
    const int* row = ei;             // source nodes
    const int* col = ei + n_edges;   // target nodes
    const int half = n_nodes / 2;

    // Persistent side stream + events (host objects; created once)
    static cudaStream_t s1 = nullptr;
    static cudaEvent_t evF = nullptr, evA = nullptr, evD = nullptr, evS1 = nullptr;
    if (s1 == nullptr) {
        cudaStreamCreateWithFlags(&s1, cudaStreamNonBlocking);
        cudaEventCreateWithFlags(&evF, cudaEventDisableTiming);
        cudaEventCreateWithFlags(&evA, cudaEventDisableTiming);
        cudaEventCreateWithFlags(&evD, cudaEventDisableTiming);
        cudaEventCreateWithFlags(&evS1, cudaEventDisableTiming);
    }

    const int T = 256;
    const int edge_threads = (n_edges + 3) / 4;
    const int scat_blocks  = (edge_threads + T - 1) / T;
    const int deg_blocks   = scat_blocks;
    const int zero4        = out_size / 4;
    const int nodeA_blocks = (half + T - 1) / T;
    const int nodeB_blocks = (n_nodes - half + T - 1) / T;
    const int node_blocks  = (n_nodes + T - 1) / T;
    const int node2_blocks = ((n_nodes + 1) / 2 + T - 1) / T;
    auto gemm_grid = [&](int rows) { return (rows + 4 * (T / 32) - 1) / (4 * (T / 32)); };

    // fork: side stream runs zero + deg + dinv
    cudaEventRecord(evF, 0);
    cudaStreamWaitEvent(s1, evF, 0);
    zero_kernel<<<(zero4 + T - 1) / T, T, 0, s1>>>((float4*)out, zero4);
    deg_kernel<<<deg_blocks, T, 0, s1>>>(col, n_edges);
    dinv_kernel<<<node_blocks, T, 0, s1>>>(n_nodes);
    cudaEventRecord(evD, s1);

    // main stream: prep, GEMM first half
    prep_kernel<<<1, 512>>>(W1, b1, W2, b2);
    gemm_kernel<<<gemm_grid(half), T>>>(x, 0, half);
    cudaEventRecord(evA, 0);

    // side stream: pack_A + scatter1 (r < half), concurrent with GEMM_B
    cudaStreamWaitEvent(s1, evA, 0);
    pack_kernel<<<nodeA_blocks, T, 0, s1>>>(0, half);
    scatter_kernel<<<scat_blocks, T, 0, s1>>>(row, col, out, n_edges, 0, half);
    cudaEventRecord(evS1, s1);

    // main stream: GEMM second half, pack_B, scatter2, finalize
    gemm_kernel<<<gemm_grid(n_nodes - half), T>>>(x, half, n_nodes - half);
    cudaStreamWaitEvent(0, evD, 0);
    pack_kernel<<<nodeB_blocks, T>>>(half, n_nodes - half);
    scatter_kernel<<<scat_blocks, T>>>(row, col, out, n_edges, half, n_nodes);
    cudaStreamWaitEvent(0, evS1, 0);
    finalize_kernel<<<node2_blocks, T>>>(out, n_nodes);
}

// round 16
// speedup vs baseline: 1.0797x; 1.0797x over previous
#include <cuda_runtime.h>
#include <cuda_fp16.h>
#include <cstdint>

#define IN_CH   512
#define HID     16
#define OUT_CH  2
#define MAX_NODES 100000
#define DEG_BLOCKS 512

// Scratch (device globals; no allocation allowed)
__device__ __align__(16) float    g_s[MAX_NODES * 2]; // y = x@W12 (fp32)
__device__ __align__(16) unsigned g_sh[MAX_NODES];    // s = y*dinv packed half2
__device__ __align__(16) int      g_deg[MAX_NODES];   // zero-init; re-zeroed in finalize
__device__ __align__(16) float    g_dinv[MAX_NODES];  // 1/sqrt(deg+1)
__device__ __align__(16) float    g_w0[IN_CH];        // col 0 of W12 = W1@W2
__device__ __align__(16) float    g_w1[IN_CH];        // col 1 of W12
__device__ float g_c[2];                              // b1@W2 + b2

// ---------------------------------------------------------------------------
// K1: fold weights/bias — 4 blocks x 128 threads, float4 W1 loads
__global__ void prep_kernel(const float* __restrict__ W1,
                            const float* __restrict__ b1,
                            const float* __restrict__ W2,
                            const float* __restrict__ b2) {
    cudaTriggerProgrammaticLaunchCompletion();   // let fused spin up now
    int t = blockIdx.x * blockDim.x + threadIdx.x;   // 0..511 == channel
    // W1 row t: 16 floats = 64 contiguous aligned bytes -> 4x float4
    const float4* w14 = reinterpret_cast<const float4*>(W1) + t * 4;
    float4 v0 = __ldg(w14 + 0);
    float4 v1 = __ldg(w14 + 1);
    float4 v2 = __ldg(w14 + 2);
    float4 v3 = __ldg(w14 + 3);
    float s0, s1;
    {
        const float* w = W2;   // broadcast loads, cache-hot after first warp
        s0 = v0.x * w[0]  + v0.y * w[2]  + v0.z * w[4]  + v0.w * w[6]
           + v1.x * w[8]  + v1.y * w[10] + v1.z * w[12] + v1.w * w[14]
           + v2.x * w[16] + v2.y * w[18] + v2.z * w[20] + v2.w * w[22]
           + v3.x * w[24] + v3.y * w[26] + v3.z * w[28] + v3.w * w[30];
        s1 = v0.x * w[1]  + v0.y * w[3]  + v0.z * w[5]  + v0.w * w[7]
           + v1.x * w[9]  + v1.y * w[11] + v1.z * w[13] + v1.w * w[15]
           + v2.x * w[17] + v2.y * w[19] + v2.z * w[21] + v2.w * w[23]
           + v3.x * w[25] + v3.y * w[27] + v3.z * w[29] + v3.w * w[31];
    }
    g_w0[t] = s0;
    g_w1[t] = s1;
    if (t < OUT_CH) {
        float c = b2[t];
#pragma unroll
        for (int h = 0; h < HID; h++) c += b1[h] * W2[h * OUT_CH + t];
        g_c[t] = c;
    }
}

// ---------------------------------------------------------------------------
// K2: fused  deg (512 blocks, no prep dependency)  ||  GEMM (PDL-syncs on prep)
__global__ void __launch_bounds__(256, 2)
fused_kernel(const float* __restrict__ x,
             const int* __restrict__ col,
             int n_edges, int n_nodes) {
    cudaTriggerProgrammaticLaunchCompletion();   // let nodeprep spin up early

    if ((int)blockIdx.x < DEG_BLOCKS) {
        int n4 = n_edges >> 2;
        int stride = DEG_BLOCKS * blockDim.x;
        for (int t = blockIdx.x * blockDim.x + threadIdx.x; t < n4; t += stride) {
            int4 c = __ldcs(reinterpret_cast<const int4*>(col) + t);
            atomicAdd(&g_deg[c.x], 1);
            atomicAdd(&g_deg[c.y], 1);
            atomicAdd(&g_deg[c.z], 1);
            atomicAdd(&g_deg[c.w], 1);
        }
        if (blockIdx.x == 0 && threadIdx.x < (n_edges & 3)) {
            atomicAdd(&g_deg[col[(n4 << 2) + threadIdx.x]], 1);
        }
        return;
    }

    cudaGridDependencySynchronize();   // GEMM consumes prep's weights

    const int lane  = threadIdx.x & 31;
    const int gwarp = (((blockIdx.x - DEG_BLOCKS) * blockDim.x) + threadIdx.x) >> 5;
    const int rbase = gwarp * 4;
    if (rbase >= n_nodes) return;

    float4 wa[4], wb[4];
#pragma unroll
    for (int j = 0; j < 4; j++) {
        int idx = lane + 32 * j;
        wa[j] = reinterpret_cast<const float4*>(g_w0)[idx];
        wb[j] = reinterpret_cast<const float4*>(g_w1)[idx];
    }

    const float4* x4 = reinterpret_cast<const float4*>(x);

    if (rbase + 4 <= n_nodes) {
        float4 v[4][4];
#pragma unroll
        for (int r = 0; r < 4; r++) {
            const float4* xr = x4 + (size_t)(rbase + r) * (IN_CH / 4);
#pragma unroll
            for (int j = 0; j < 4; j++) v[r][j] = __ldcs(xr + lane + 32 * j);
        }
        float s00 = 0.f, s01 = 0.f, s10 = 0.f, s11 = 0.f;
        float s20 = 0.f, s21 = 0.f, s30 = 0.f, s31 = 0.f;
#pragma unroll
        for (int j = 0; j < 4; j++) {
            s00 += v[0][j].x * wa[j].x + v[0][j].y * wa[j].y + v[0][j].z * wa[j].z + v[0][j].w * wa[j].w;
            s01 += v[0][j].x * wb[j].x + v[0][j].y * wb[j].y + v[0][j].z * wb[j].z + v[0][j].w * wb[j].w;
            s10 += v[1][j].x * wa[j].x + v[1][j].y * wa[j].y + v[1][j].z * wa[j].z + v[1][j].w * wa[j].w;
            s11 += v[1][j].x * wb[j].x + v[1][j].y * wb[j].y + v[1][j].z * wb[j].z + v[1][j].w * wb[j].w;
            s20 += v[2][j].x * wa[j].x + v[2][j].y * wa[j].y + v[2][j].z * wa[j].z + v[2][j].w * wa[j].w;
            s21 += v[2][j].x * wb[j].x + v[2][j].y * wb[j].y + v[2][j].z * wb[j].z + v[2][j].w * wb[j].w;
            s30 += v[3][j].x * wa[j].x + v[3][j].y * wa[j].y + v[3][j].z * wa[j].z + v[3][j].w * wa[j].w;
            s31 += v[3][j].x * wb[j].x + v[3][j].y * wb[j].y + v[3][j].z * wb[j].z + v[3][j].w * wb[j].w;
        }
#pragma unroll
        for (int off = 16; off > 0; off >>= 1) {
            s00 += __shfl_xor_sync(0xFFFFFFFFu, s00, off);
            s01 += __shfl_xor_sync(0xFFFFFFFFu, s01, off);
            s10 += __shfl_xor_sync(0xFFFFFFFFu, s10, off);
            s11 += __shfl_xor_sync(0xFFFFFFFFu, s11, off);
            s20 += __shfl_xor_sync(0xFFFFFFFFu, s20, off);
            s21 += __shfl_xor_sync(0xFFFFFFFFu, s21, off);
            s30 += __shfl_xor_sync(0xFFFFFFFFu, s30, off);
            s31 += __shfl_xor_sync(0xFFFFFFFFu, s31, off);
        }
        if (lane < 4) {
            float o0, o1;
            if      (lane == 0) { o0 = s00; o1 = s01; }
            else if (lane == 1) { o0 = s10; o1 = s11; }
            else if (lane == 2) { o0 = s20; o1 = s21; }
            else                { o0 = s30; o1 = s31; }
            reinterpret_cast<float2*>(g_s)[rbase + lane] = make_float2(o0, o1);
        }
    } else {
        for (int row = rbase; row < n_nodes; row++) {
            const float4* xr = x4 + (size_t)row * (IN_CH / 4);
            float s0 = 0.f, s1 = 0.f;
#pragma unroll
            for (int j = 0; j < 4; j++) {
                float4 v0 = __ldcs(xr + lane + 32 * j);
                s0 += v0.x * wa[j].x + v0.y * wa[j].y + v0.z * wa[j].z + v0.w * wa[j].w;
                s1 += v0.x * wb[j].x + v0.y * wb[j].y + v0.z * wb[j].z + v0.w * wb[j].w;
            }
#pragma unroll
            for (int off = 16; off > 0; off >>= 1) {
                s0 += __shfl_xor_sync(0xFFFFFFFFu, s0, off);
                s1 += __shfl_xor_sync(0xFFFFFFFFu, s1, off);
            }
            if (lane == 0)
                reinterpret_cast<float2*>(g_s)[row] = make_float2(s0, s1);
        }
    }
}

// ---------------------------------------------------------------------------
// K3: node prep (2 nodes/thread): dinv; s = y*dinv; out seed = s; pack half2
__global__ void nodeprep_kernel(float* __restrict__ out, int n_nodes) {
    cudaTriggerProgrammaticLaunchCompletion();   // let scatter spin up early
    cudaGridDependencySynchronize();
    int i = (blockIdx.x * blockDim.x + threadIdx.x) * 2;
    if (i + 1 < n_nodes) {
        float4 y = *reinterpret_cast<float4*>(g_s + i * 2);
        float d0 = rsqrtf((float)(g_deg[i] + 1));
        float d1 = rsqrtf((float)(g_deg[i + 1] + 1));
        y.x *= d0; y.y *= d0; y.z *= d1; y.w *= d1;
        *reinterpret_cast<float4*>(out + i * 2) = y;   // self-loop seed, fp32
        __half2 h0 = __floats2half2_rn(y.x, y.y);
        __half2 h1 = __floats2half2_rn(y.z, y.w);
        uint2 p = make_uint2(*reinterpret_cast<unsigned*>(&h0),
                             *reinterpret_cast<unsigned*>(&h1));
        *reinterpret_cast<uint2*>(g_sh + i) = p;
        *reinterpret_cast<float2*>(g_dinv + i) = make_float2(d0, d1);
    } else if (i < n_nodes) {
        float di = rsqrtf((float)(g_deg[i] + 1));
        g_dinv[i] = di;
        float2 y = reinterpret_cast<const float2*>(g_s)[i];
        float2 s = make_float2(y.x * di, y.y * di);
        reinterpret_cast<float2*>(out)[i] = s;
        __half2 h = __floats2half2_rn(s.x, s.y);
        g_sh[i] = *reinterpret_cast<unsigned*>(&h);
    }
}

// ---------------------------------------------------------------------------
// K4: edge scatter  out[c] += s[r]   (4 edges/thread; 4B half2 gathers)
__global__ void scatter_kernel(const int* __restrict__ row,
                               const int* __restrict__ col,
                               float* __restrict__ out, int n_edges) {
    cudaTriggerProgrammaticLaunchCompletion();   // let finalize spin up early
    cudaGridDependencySynchronize();
    int t = blockIdx.x * blockDim.x + threadIdx.x;
    int e = t * 4;
    if (e + 3 < n_edges) {
        int4 r = __ldg(reinterpret_cast<const int4*>(row + e));
        int4 c = __ldg(reinterpret_cast<const int4*>(col + e));

        unsigned p0 = __ldg(g_sh + r.x);
        unsigned p1 = __ldg(g_sh + r.y);
        unsigned p2 = __ldg(g_sh + r.z);
        unsigned p3 = __ldg(g_sh + r.w);
        float2 sx = __half22float2(*reinterpret_cast<__half2*>(&p0));
        float2 sy = __half22float2(*reinterpret_cast<__half2*>(&p1));
        float2 sz = __half22float2(*reinterpret_cast<__half2*>(&p2));
        float2 sw = __half22float2(*reinterpret_cast<__half2*>(&p3));

        asm volatile("red.global.add.v2.f32 [%0], {%1, %2};"
                     :: "l"(out + (size_t)c.x * 2), "f"(sx.x), "f"(sx.y) : "memory");
        asm volatile("red.global.add.v2.f32 [%0], {%1, %2};"
                     :: "l"(out + (size_t)c.y * 2), "f"(sy.x), "f"(sy.y) : "memory");
        asm volatile("red.global.add.v2.f32 [%0], {%1, %2};"
                     :: "l"(out + (size_t)c.z * 2), "f"(sz.x), "f"(sz.y) : "memory");
        asm volatile("red.global.add.v2.f32 [%0], {%1, %2};"
                     :: "l"(out + (size_t)c.w * 2), "f"(sw.x), "f"(sw.y) : "memory");
    } else {
        for (; e < n_edges; e++) {
            int r1 = row[e], c1 = col[e];
            unsigned p = __ldg(g_sh + r1);
            float2 sv = __half22float2(*reinterpret_cast<__half2*>(&p));
            asm volatile("red.global.add.v2.f32 [%0], {%1, %2};"
                         :: "l"(out + (size_t)c1 * 2), "f"(sv.x), "f"(sv.y) : "memory");
        }
    }
}

// ---------------------------------------------------------------------------
// K5: finalize (2 nodes/thread): out = out*dinv + c; re-zero g_deg
__global__ void finalize_kernel(float* __restrict__ out, int n_nodes) {
    cudaGridDependencySynchronize();
    int i = (blockIdx.x * blockDim.x + threadIdx.x) * 2;
    float c0 = g_c[0], c1 = g_c[1];
    if (i + 1 < n_nodes) {
        float4 a = *reinterpret_cast<float4*>(out + i * 2);
        float2 d = *reinterpret_cast<float2*>(g_dinv + i);
        a.x = a.x * d.x + c0;  a.y = a.y * d.x + c1;
        a.z = a.z * d.y + c0;  a.w = a.w * d.y + c1;
        *reinterpret_cast<float4*>(out + i * 2) = a;
        *reinterpret_cast<int2*>(g_deg + i) = make_int2(0, 0);  // ready for next run
    } else if (i < n_nodes) {
        float di = g_dinv[i];
        float2 a = reinterpret_cast<float2*>(out)[i];
        a.x = a.x * di + c0;
        a.y = a.y * di + c1;
        reinterpret_cast<float2*>(out)[i] = a;
        g_deg[i] = 0;
    }
}

// ---------------------------------------------------------------------------
static inline void launch_pdl(const void* fn, dim3 grid, dim3 block,
                              void** args, cudaStream_t stream) {
    cudaLaunchConfig_t cfg = {};
    cfg.gridDim = grid;
    cfg.blockDim = block;
    cfg.dynamicSmemBytes = 0;
    cfg.stream = stream;
    cudaLaunchAttribute attr[1];
    attr[0].id = cudaLaunchAttributeProgrammaticStreamSerialization;
    attr[0].val.programmaticStreamSerializationAllowed = 1;
    cfg.attrs = attr;
    cfg.numAttrs = 1;
    cudaLaunchKernelExC(&cfg, fn, args);
}

extern "C" void kernel_launch(void* const* d_in, const int* in_sizes, int n_in,
                              void* d_out, int out_size) {
    const float* x  = (const float*)d_in[0];
    const int*   ei = (const int*)d_in[1];   // [2, E]
    const float* W1 = (const float*)d_in[2];
    const float* b1 = (const float*)d_in[3];
    const float* W2 = (const float*)d_in[4];
    const float* b2 = (const float*)d_in[5];
    float* out = (float*)d_out;

    const int n_edges = in_sizes[1] / 2;
    const int n_nodes = out_size / OUT_CH;
    const int* row = ei;             // source nodes
    const int* col = ei + n_edges;   // target nodes

    const int T = 256;
    const int edge_threads = (n_edges + 3) / 4;
    const int gemm_blocks  = (n_nodes + 4 * (T / 32) - 1) / (4 * (T / 32));
    const int node2_blocks = ((n_nodes + 1) / 2 + T - 1) / T;
    const int scat_blocks  = (edge_threads + T - 1) / T;

    prep_kernel<<<4, 128>>>(W1, b1, W2, b2);

    {
        void* args[] = {(void*)&x, (void*)&col, (void*)&n_edges, (void*)&n_nodes};
        launch_pdl((const void*)fused_kernel,
                   dim3(DEG_BLOCKS + gemm_blocks), dim3(T), args, 0);
    }
    {
        void* args[] = {(void*)&out, (void*)&n_nodes};
        launch_pdl((const void*)nodeprep_kernel, dim3(node2_blocks), dim3(T), args, 0);
    }
    {
        void* args[] = {(void*)&row, (void*)&col, (void*)&out, (void*)&n_edges};
        launch_pdl((const void*)scatter_kernel, dim3(scat_blocks), dim3(T), args, 0);
    }
    {
        void* args[] = {(void*)&out, (void*)&n_nodes};
        launch_pdl((const void*)finalize_kernel, dim3(node2_blocks), dim3(T), args, 0);
    }
}